// round 13
// baseline (speedup 1.0000x reference)
#include <cuda_runtime.h>
#include <cuda_fp16.h>
#include <math.h>
#include <stdint.h>

#define B_  32
#define N_  512
#define M_  512
#define D_  1024

// ---------------------------------------------------------------------------
// Scratch (__device__ globals — allocation-free rule)
// ---------------------------------------------------------------------------
__device__ __align__(256) float g_S [(size_t)B_ * N_ * M_];   // raw logits [n, m]
__device__ __align__(256) float g_St[(size_t)B_ * N_ * M_];   // raw logits [m, n]

// ---------------------------------------------------------------------------
// helpers (plain sm_80+ features — valid on sm_103 non-'a' target)
// ---------------------------------------------------------------------------
__device__ __forceinline__ uint32_t smem_u32(const void* p) {
    uint32_t a;
    asm("{ .reg .u64 t; cvta.to.shared.u64 t, %1; cvt.u32.u64 %0, t; }" : "=r"(a) : "l"(p));
    return a;
}
__device__ __forceinline__ void cp16(uint32_t dst, const void* gsrc) {
    asm volatile("cp.async.cg.shared.global [%0], [%1], 16;" :: "r"(dst), "l"(gsrc) : "memory");
}
__device__ __forceinline__ void cp_commit() { asm volatile("cp.async.commit_group;" ::: "memory"); }
template <int NW> __device__ __forceinline__ void cp_wait() {
    asm volatile("cp.async.wait_group %0;" :: "n"(NW) : "memory");
}
__device__ __forceinline__ void ldsm4(uint32_t* r, uint32_t addr) {
    asm volatile("ldmatrix.sync.aligned.m8n8.x4.shared.b16 {%0,%1,%2,%3}, [%4];"
                 : "=r"(r[0]), "=r"(r[1]), "=r"(r[2]), "=r"(r[3]) : "r"(addr));
}
__device__ __forceinline__ void mma16816(float* c, const uint32_t* a, uint32_t b0, uint32_t b1) {
    asm volatile(
        "mma.sync.aligned.m16n8k16.row.col.f32.f16.f16.f32 "
        "{%0,%1,%2,%3}, {%4,%5,%6,%7}, {%8,%9}, {%0,%1,%2,%3};"
        : "+f"(c[0]), "+f"(c[1]), "+f"(c[2]), "+f"(c[3])
        : "r"(a[0]), "r"(a[1]), "r"(a[2]), "r"(a[3]), "r"(b0), "r"(b1));
}

// 32B-row tile swizzle: conflict-free for both STS.128 and ldmatrix phases
__device__ __forceinline__ uint32_t sw16(int row, int c) {
    return (uint32_t)(row * 32 + ((c ^ ((row >> 2) & 1)) << 4));
}

__device__ __forceinline__ void cvt8(const float4 v0, const float4 v1,
                                     uint4& hi, uint4& lo)
{
    __half2 h0 = __floats2half2_rn(v0.x, v0.y);
    __half2 h1 = __floats2half2_rn(v0.z, v0.w);
    __half2 h2 = __floats2half2_rn(v1.x, v1.y);
    __half2 h3 = __floats2half2_rn(v1.z, v1.w);
    float2 f0 = __half22float2(h0), f1 = __half22float2(h1);
    float2 f2 = __half22float2(h2), f3 = __half22float2(h3);
    __half2 l0 = __floats2half2_rn(v0.x - f0.x, v0.y - f0.y);
    __half2 l1 = __floats2half2_rn(v0.z - f1.x, v0.w - f1.y);
    __half2 l2 = __floats2half2_rn(v1.x - f2.x, v1.y - f2.y);
    __half2 l3 = __floats2half2_rn(v1.z - f3.x, v1.w - f3.y);
    hi.x = *reinterpret_cast<uint32_t*>(&h0);  hi.y = *reinterpret_cast<uint32_t*>(&h1);
    hi.z = *reinterpret_cast<uint32_t*>(&h2);  hi.w = *reinterpret_cast<uint32_t*>(&h3);
    lo.x = *reinterpret_cast<uint32_t*>(&l0);  lo.y = *reinterpret_cast<uint32_t*>(&l1);
    lo.z = *reinterpret_cast<uint32_t*>(&l2);  lo.w = *reinterpret_cast<uint32_t*>(&l3);
}

// ---------------------------------------------------------------------------
// Warp-specialized fp32->fp16-split HMMA GEMM (NT) + fused transpose epilogue.
// CTA tile 64(n) x 128(m), K-step 16. 192 threads:
//   warps 0-3: mma only (warp tile 64x32)
//   warps 4-5: loaders — cp.async fp32 (2 steps ahead) -> LDS -> cvt8 -> STS fp16
// Per-loader-thread staging slot = 12 x 16B chunks = 192 B:
//   chunks 0-3: A row-groups s=0,1 (2 chunks each)
//   chunks 4-11: B row-groups s=0..3 (2 chunks each)
// ---------------------------------------------------------------------------
#define TILE_AH 0
#define TILE_AL 2048
#define TILE_BH 4096
#define TILE_BL 8192
#define F16_STAGE 12288
#define F32_BASE  24576
#define F32_STAGE 12288
#define SLOT      192
#define GEMM_SMEM 49152

__global__ __launch_bounds__(192, 2)
void gemm_ws(const float* __restrict__ X1, const float* __restrict__ X2,
             float* __restrict__ S, float* __restrict__ St)
{
    extern __shared__ __align__(128) char smem[];
    const uint32_t sb = smem_u32(smem);
    const int tid  = threadIdx.x;
    const int warp = tid >> 5;
    const int lane = tid & 31;
    const int b    = blockIdx.z;
    const int rA0  = blockIdx.y * 64;    // n
    const int rB0  = blockIdx.x * 128;   // m

    const bool is_mma = (warp < 4);
    const int T = D_ >> 4;               // 64 K-steps of 16

    // ---------------- loader setup (warps 4-5; tid2 in 0..63) ----------------
    const int tid2 = tid & 63;
    const int lr   = tid2 >> 1;          // row within 32-row group
    const int lc   = tid2 & 1;           // 8-fp32 chunk within 16
    const float* aL = X1 + (size_t)b * N_ * D_ + (size_t)(rA0 + lr) * D_ + lc * 8;
    const float* bL = X2 + (size_t)b * M_ * D_ + (size_t)(rB0 + lr) * D_ + lc * 8;
    const uint32_t slot = (uint32_t)tid2 * SLOT;

    // issue 12 cp.async chunks for K-step starting at k0
#define LDR_CP(stg, k0)                                                           \
    do {                                                                          \
        const uint32_t d = sb + F32_BASE + (uint32_t)(stg) * F32_STAGE + slot;    \
        _Pragma("unroll")                                                         \
        for (int s = 0; s < 2; s++) {                                             \
            cp16(d + (s * 2 + 0) * 16, aL + (size_t)s * 32 * D_ + (k0));          \
            cp16(d + (s * 2 + 1) * 16, aL + (size_t)s * 32 * D_ + (k0) + 4);      \
        }                                                                         \
        _Pragma("unroll")                                                         \
        for (int s = 0; s < 4; s++) {                                             \
            cp16(d + (4 + s * 2 + 0) * 16, bL + (size_t)s * 32 * D_ + (k0));      \
            cp16(d + (4 + s * 2 + 1) * 16, bL + (size_t)s * 32 * D_ + (k0) + 4);  \
        }                                                                         \
        cp_commit();                                                              \
    } while (0)

    // convert staging(stg) -> fp16 stage(fs)
#define LDR_CVT(stg, fs)                                                          \
    do {                                                                          \
        const char* sp = smem + F32_BASE + (stg) * F32_STAGE + slot;              \
        char* fo = smem + (fs) * F16_STAGE;                                       \
        _Pragma("unroll")                                                         \
        for (int s = 0; s < 2; s++) {                                             \
            float4 v0 = *reinterpret_cast<const float4*>(sp + (s * 2 + 0) * 16);  \
            float4 v1 = *reinterpret_cast<const float4*>(sp + (s * 2 + 1) * 16);  \
            uint4 hi, lo;                                                         \
            cvt8(v0, v1, hi, lo);                                                 \
            const uint32_t sw = sw16(lr + s * 32, lc);                            \
            *reinterpret_cast<uint4*>(fo + TILE_AH + sw) = hi;                    \
            *reinterpret_cast<uint4*>(fo + TILE_AL + sw) = lo;                    \
        }                                                                         \
        _Pragma("unroll")                                                         \
        for (int s = 0; s < 4; s++) {                                             \
            float4 v0 = *reinterpret_cast<const float4*>(sp + (4 + s * 2 + 0) * 16); \
            float4 v1 = *reinterpret_cast<const float4*>(sp + (4 + s * 2 + 1) * 16); \
            uint4 hi, lo;                                                         \
            cvt8(v0, v1, hi, lo);                                                 \
            const uint32_t sw = sw16(lr + s * 32, lc);                            \
            *reinterpret_cast<uint4*>(fo + TILE_BH + sw) = hi;                    \
            *reinterpret_cast<uint4*>(fo + TILE_BL + sw) = lo;                    \
        }                                                                         \
    } while (0)

    // ---------------- mma setup (warps 0-3) ----------------
    const int warp_n = (warp & 3) << 5;      // B-row (m) offset: 0,32,64,96
    const int arow = lane & 15;
    const int acx  = (lane >> 4) & 1;
    const int brow = (lane & 7) + ((lane & 16) >> 1);
    const int bcx  = (lane >> 3) & 1;

    float acc[4][4][4];
#pragma unroll
    for (int i = 0; i < 4; i++)
#pragma unroll
        for (int j = 0; j < 4; j++)
#pragma unroll
            for (int q = 0; q < 4; q++) acc[i][j][q] = 0.f;

    // ---------------- prologue (loaders) ----------------
    if (!is_mma) {
        LDR_CP(0, 0);            // step 0 -> staging 0
        LDR_CP(1, 16);           // step 1 -> staging 1
        cp_wait<1>();            // step 0 staged (own data, per-thread wait ok)
        LDR_CVT(0, 0);           // fp16 stage 0 ready (visible after syncthreads)
    }

    // ---------------- main loop: one barrier per step ----------------
    for (int t = 0; t < T; t++) {
        __syncthreads();         // fp16 stage t&1 visible; prior reads of (t+1)&1 done

        if (is_mma) {
            const uint32_t st = sb + (uint32_t)(t & 1) * F16_STAGE;
            uint32_t BH[2][4], BL[2][4];
#pragma unroll
            for (int j = 0; j < 2; j++) {
                ldsm4(BH[j], st + TILE_BH + sw16(warp_n + j * 16 + brow, bcx));
                ldsm4(BL[j], st + TILE_BL + sw16(warp_n + j * 16 + brow, bcx));
            }
#pragma unroll
            for (int i = 0; i < 4; i++) {
                uint32_t AHr[4], ALr[4];
                ldsm4(AHr, st + TILE_AH + sw16(i * 16 + arow, acx));
                ldsm4(ALr, st + TILE_AL + sw16(i * 16 + arow, acx));
#pragma unroll
                for (int j = 0; j < 4; j++) {
                    const uint32_t bh0 = BH[j >> 1][(j & 1) * 2];
                    const uint32_t bh1 = BH[j >> 1][(j & 1) * 2 + 1];
                    const uint32_t bl0 = BL[j >> 1][(j & 1) * 2];
                    const uint32_t bl1 = BL[j >> 1][(j & 1) * 2 + 1];
                    mma16816(acc[i][j], AHr, bh0, bh1);   // hi*hi
                    mma16816(acc[i][j], AHr, bl0, bl1);   // hi*lo
                    mma16816(acc[i][j], ALr, bh0, bh1);   // lo*hi
                }
            }
        } else {
            // staging buffer for step s is (s & 1); write (t+2), read (t+1): disjoint
            if (t + 2 < T) LDR_CP(t & 1, (t + 2) << 4);
            if (t + 1 < T) {
                if (t + 2 < T) cp_wait<1>(); else cp_wait<0>();   // step t+1 staged
                LDR_CVT((t + 1) & 1, (t + 1) & 1);
            }
        }
    }

    // ---------------- epilogue: S from regs; St via 64x129 smem transpose ----
    float* Sb = S + (size_t)b * N_ * M_;
    const int tr = lane >> 2;
    const int tc = (lane & 3) * 2;

    if (is_mma) {
#pragma unroll
        for (int i = 0; i < 4; i++) {
#pragma unroll
            for (int j = 0; j < 4; j++) {
                const int r = i * 16 + tr;            // local n (0..63)
                const int c = warp_n + j * 8 + tc;    // local m (0..127)
                *reinterpret_cast<float2*>(Sb + (size_t)(rA0 + r) * M_ + rB0 + c) =
                    make_float2(acc[i][j][0], acc[i][j][1]);
                *reinterpret_cast<float2*>(Sb + (size_t)(rA0 + r + 8) * M_ + rB0 + c) =
                    make_float2(acc[i][j][2], acc[i][j][3]);
            }
        }
    }

    __syncthreads();                                  // last-stage ldsm done -> smem reusable
    float* epi = reinterpret_cast<float*>(smem);      // [64][129]
    if (is_mma) {
#pragma unroll
        for (int i = 0; i < 4; i++)
#pragma unroll
            for (int j = 0; j < 4; j++) {
                const int r = i * 16 + tr;
                const int c = warp_n + j * 8 + tc;
                epi[r * 129 + c]           = acc[i][j][0];
                epi[r * 129 + c + 1]       = acc[i][j][1];
                epi[(r + 8) * 129 + c]     = acc[i][j][2];
                epi[(r + 8) * 129 + c + 1] = acc[i][j][3];
            }
    }
    __syncthreads();

    if (tid < 128) {                                  // one thread per m-column
        float* Stb = St + (size_t)b * N_ * M_ + (size_t)(rB0 + tid) * N_ + rA0;
#pragma unroll
        for (int i = 0; i < 16; i++) {
            float4 v;
            v.x = epi[(i * 4 + 0) * 129 + tid];
            v.y = epi[(i * 4 + 1) * 129 + tid];
            v.z = epi[(i * 4 + 2) * 129 + tid];
            v.w = epi[(i * 4 + 3) * 129 + tid];
            *reinterpret_cast<float4*>(Stb + i * 4) = v;
        }
    }
}

// ---------------------------------------------------------------------------
// Warp-per-row fused masked softmax + near-one-hot sparse apply
// (R8 version verbatim — measured 59.5us). Both directions in one launch.
// ---------------------------------------------------------------------------
#define TAU 1e-7f
#define LCAP 512     // worst-case significant entries per row (correctness bound)

__global__ __launch_bounds__(256)
void softmax_apply3(const float* __restrict__ S, const float* __restrict__ St,
                    const int* __restrict__ mask1, const int* __restrict__ mask2,
                    const float* __restrict__ x1, const float* __restrict__ x2,
                    float* __restrict__ out)
{
    __shared__ float sp  [8][LCAP];
    __shared__ int   sidx[8][LCAP];

    const int dir  = blockIdx.y;
    const int warp = threadIdx.x >> 5;
    const int lane = threadIdx.x & 31;
    const int row  = blockIdx.x * 8 + warp;      // 0 .. B*512-1
    const int b    = row >> 9;

    const float* Sr = (dir ? St : S) + (size_t)row * 512;
    const int*   mk = (dir ? mask1 : mask2) + (size_t)b * 512;
    const float* Xb = (dir ? x1 : x2) + (size_t)b * 512 * D_;
    float*       op = out + (size_t)dir * B_ * N_ * D_ + (size_t)row * D_;

    // ---- load 16 logits/lane + mask, fold mask, find max ----
    const float4* Sr4 = reinterpret_cast<const float4*>(Sr);
    const int4*   mk4 = reinterpret_cast<const int4*>(mk);
    float v[16];
    float mx = -INFINITY;
#pragma unroll
    for (int i = 0; i < 4; i++) {
        const float4 f = Sr4[i * 32 + lane];
        const int4   m = mk4[i * 32 + lane];
        v[i * 4 + 0] = m.x ? f.x : -INFINITY;
        v[i * 4 + 1] = m.y ? f.y : -INFINITY;
        v[i * 4 + 2] = m.z ? f.z : -INFINITY;
        v[i * 4 + 3] = m.w ? f.w : -INFINITY;
        mx = fmaxf(mx, fmaxf(fmaxf(v[i*4], v[i*4+1]), fmaxf(v[i*4+2], v[i*4+3])));
    }
#pragma unroll
    for (int s = 16; s > 0; s >>= 1) mx = fmaxf(mx, __shfl_xor_sync(0xffffffffu, mx, s));

    // ---- exp + sum ----
    float sum = 0.f;
#pragma unroll
    for (int i = 0; i < 16; i++) {
        const float e = (v[i] == -INFINITY) ? 0.f : __expf(v[i] - mx);
        v[i] = e;
        sum += e;
    }
#pragma unroll
    for (int s = 16; s > 0; s >>= 1) sum += __shfl_xor_sync(0xffffffffu, sum, s);
    const float inv = 1.f / sum;

    // ---- per-warp deterministic significant list (ballot prefix) ----
    int cnt = 0;
#pragma unroll
    for (int j = 0; j < 16; j++) {
        const int i = j >> 2, c = j & 3;               // element idx = i*128 + lane*4 + c
        const float p = v[i * 4 + c] * inv;
        const bool sig = p > TAU;
        const unsigned bm = __ballot_sync(0xffffffffu, sig);
        if (sig) {
            const int pos = cnt + __popc(bm & ((1u << lane) - 1u));
            sidx[warp][pos] = i * 128 + lane * 4 + c;
            sp[warp][pos]   = p;
        }
        cnt += __popc(bm);
    }
    __syncwarp();

    // ---- gather-accumulate: out[row,:] = sum_i p_i * X[k_i,:] ----
    float4 A[8];
#pragma unroll
    for (int u = 0; u < 8; u++) A[u] = make_float4(0.f, 0.f, 0.f, 0.f);

    const float4* Xb4 = reinterpret_cast<const float4*>(Xb);
    for (int i = 0; i < cnt; i++) {
        const float p = sp[warp][i];
        const int   k = sidx[warp][i];
        const float4* xr = Xb4 + (size_t)k * (D_ / 4);
#pragma unroll
        for (int u = 0; u < 8; u++) {
            const float4 xv = xr[u * 32 + lane];
            A[u].x += p * xv.x;  A[u].y += p * xv.y;
            A[u].z += p * xv.z;  A[u].w += p * xv.w;
        }
    }

    float4* op4 = reinterpret_cast<float4*>(op);
#pragma unroll
    for (int u = 0; u < 8; u++) op4[u * 32 + lane] = A[u];
}

// ---------------------------------------------------------------------------
extern "C" void kernel_launch(void* const* d_in, const int* in_sizes, int n_in,
                              void* d_out, int out_size)
{
    const float* x1    = (const float*)d_in[0];
    const float* x2    = (const float*)d_in[1];
    const int*   mask1 = (const int*)  d_in[2];
    const int*   mask2 = (const int*)  d_in[3];

    float* out = (float*)d_out;

    float *S, *St;
    cudaGetSymbolAddress((void**)&S,  g_S);
    cudaGetSymbolAddress((void**)&St, g_St);

    cudaFuncSetAttribute(gemm_ws, cudaFuncAttributeMaxDynamicSharedMemorySize, GEMM_SMEM);

    // 1) S = x1 @ x2^T and St = S^T (warp-specialized producer/consumer GEMM)
    gemm_ws<<<dim3(M_ / 128, N_ / 64, B_), 192, GEMM_SMEM>>>(x1, x2, S, St);

    // 2) warp-per-row fused masked-softmax + sparse apply (R8, both dirs)
    softmax_apply3<<<dim3(B_ * N_ / 8, 2), 256>>>(S, St, mask1, mask2, x1, x2, out);
}

// round 14
// speedup vs baseline: 1.7355x; 1.7355x over previous
#include <cuda_runtime.h>
#include <cuda_fp16.h>
#include <math.h>
#include <stdint.h>

#define B_  32
#define N_  512
#define M_  512
#define D_  1024

// ---------------------------------------------------------------------------
// Scratch (__device__ globals — allocation-free rule)
// ---------------------------------------------------------------------------
__device__ __align__(256) float g_S [(size_t)B_ * N_ * M_];   // raw logits [n, m]
__device__ __align__(256) float g_St[(size_t)B_ * N_ * M_];   // raw logits [m, n]

// ---------------------------------------------------------------------------
// helpers (plain sm_80+ features — valid on sm_103 non-'a' target)
// ---------------------------------------------------------------------------
__device__ __forceinline__ uint32_t smem_u32(const void* p) {
    uint32_t a;
    asm("{ .reg .u64 t; cvta.to.shared.u64 t, %1; cvt.u32.u64 %0, t; }" : "=r"(a) : "l"(p));
    return a;
}
__device__ __forceinline__ void ldsm4(uint32_t* r, uint32_t addr) {
    asm volatile("ldmatrix.sync.aligned.m8n8.x4.shared.b16 {%0,%1,%2,%3}, [%4];"
                 : "=r"(r[0]), "=r"(r[1]), "=r"(r[2]), "=r"(r[3]) : "r"(addr));
}
__device__ __forceinline__ void mma16816(float* c, const uint32_t* a, uint32_t b0, uint32_t b1) {
    asm volatile(
        "mma.sync.aligned.m16n8k16.row.col.f32.f16.f16.f32 "
        "{%0,%1,%2,%3}, {%4,%5,%6,%7}, {%8,%9}, {%0,%1,%2,%3};"
        : "+f"(c[0]), "+f"(c[1]), "+f"(c[2]), "+f"(c[3])
        : "r"(a[0]), "r"(a[1]), "r"(a[2]), "r"(a[3]), "r"(b0), "r"(b1));
}

// 32B-row tile swizzle: conflict-free for both STS.128 and ldmatrix phases
__device__ __forceinline__ uint32_t sw16(int row, int c) {
    return (uint32_t)(row * 32 + ((c ^ ((row >> 2) & 1)) << 4));
}

// ---------------------------------------------------------------------------
// Fused fp32->fp16-split HMMA GEMM (NT) + transpose epilogue
// (R7 version verbatim — measured 179.5us, best of 4 structural variants)
// ---------------------------------------------------------------------------
#define TILE_AH 0
#define TILE_AL 4096
#define TILE_BH 8192
#define TILE_BL 12288
#define STAGE_SZ 16384
#define EPI_SMEM (64 * 129 * 4)
#define GEMM_SMEM (EPI_SMEM > 2 * STAGE_SZ ? EPI_SMEM : 2 * STAGE_SZ)

__device__ __forceinline__ void cvt8(const float4 v0, const float4 v1,
                                     uint4& hi, uint4& lo)
{
    __half2 h0 = __floats2half2_rn(v0.x, v0.y);
    __half2 h1 = __floats2half2_rn(v0.z, v0.w);
    __half2 h2 = __floats2half2_rn(v1.x, v1.y);
    __half2 h3 = __floats2half2_rn(v1.z, v1.w);
    float2 f0 = __half22float2(h0), f1 = __half22float2(h1);
    float2 f2 = __half22float2(h2), f3 = __half22float2(h3);
    __half2 l0 = __floats2half2_rn(v0.x - f0.x, v0.y - f0.y);
    __half2 l1 = __floats2half2_rn(v0.z - f1.x, v0.w - f1.y);
    __half2 l2 = __floats2half2_rn(v1.x - f2.x, v1.y - f2.y);
    __half2 l3 = __floats2half2_rn(v1.z - f3.x, v1.w - f3.y);
    hi.x = *reinterpret_cast<uint32_t*>(&h0);  hi.y = *reinterpret_cast<uint32_t*>(&h1);
    hi.z = *reinterpret_cast<uint32_t*>(&h2);  hi.w = *reinterpret_cast<uint32_t*>(&h3);
    lo.x = *reinterpret_cast<uint32_t*>(&l0);  lo.y = *reinterpret_cast<uint32_t*>(&l1);
    lo.z = *reinterpret_cast<uint32_t*>(&l2);  lo.w = *reinterpret_cast<uint32_t*>(&l3);
}

__global__ __launch_bounds__(256, 2)
void gemm_fused(const float* __restrict__ X1, const float* __restrict__ X2,
                float* __restrict__ S, float* __restrict__ St)
{
    extern __shared__ __align__(128) char smem[];
    const uint32_t sb = smem_u32(smem);
    const int tid  = threadIdx.x;
    const int warp = tid >> 5;
    const int lane = tid & 31;
    const int b    = blockIdx.z;
    const int rA0  = blockIdx.y * 128;   // n
    const int rB0  = blockIdx.x * 128;   // m

    const int lrow = tid >> 1;
    const int lc   = tid & 1;
    const float* aptr = X1 + (size_t)b * N_ * D_ + (size_t)(rA0 + lrow) * D_ + lc * 8;
    const float* bptr = X2 + (size_t)b * M_ * D_ + (size_t)(rB0 + lrow) * D_ + lc * 8;
    const uint32_t swoff = sw16(lrow, lc);

    const int warp_m = (warp >> 2) << 6;
    const int warp_n = (warp & 3) << 5;

    float acc[4][4][4];
#pragma unroll
    for (int i = 0; i < 4; i++)
#pragma unroll
        for (int j = 0; j < 4; j++)
#pragma unroll
            for (int q = 0; q < 4; q++) acc[i][j][q] = 0.f;

    const int arow = lane & 15;
    const int acx  = (lane >> 4) & 1;
    const int brow = (lane & 7) + ((lane & 16) >> 1);
    const int bcx  = (lane >> 3) & 1;

    const int T = D_ >> 4;   // 64

    float4 a0 = *reinterpret_cast<const float4*>(aptr);
    float4 a1 = *reinterpret_cast<const float4*>(aptr + 4);
    float4 b0 = *reinterpret_cast<const float4*>(bptr);
    float4 b1 = *reinterpret_cast<const float4*>(bptr + 4);
    {
        uint4 hi, lo;
        cvt8(a0, a1, hi, lo);
        *reinterpret_cast<uint4*>(smem + TILE_AH + swoff) = hi;
        *reinterpret_cast<uint4*>(smem + TILE_AL + swoff) = lo;
        cvt8(b0, b1, hi, lo);
        *reinterpret_cast<uint4*>(smem + TILE_BH + swoff) = hi;
        *reinterpret_cast<uint4*>(smem + TILE_BL + swoff) = lo;
    }

    for (int t = 0; t < T; t++) {
        __syncthreads();

        const bool pf = (t + 1 < T);
        if (pf) {
            const int k0 = (t + 1) << 4;
            a0 = *reinterpret_cast<const float4*>(aptr + k0);
            a1 = *reinterpret_cast<const float4*>(aptr + k0 + 4);
            b0 = *reinterpret_cast<const float4*>(bptr + k0);
            b1 = *reinterpret_cast<const float4*>(bptr + k0 + 4);
        }

        const uint32_t st = sb + (uint32_t)(t & 1) * STAGE_SZ;
        uint32_t BH[2][4], BL[2][4];
#pragma unroll
        for (int j = 0; j < 2; j++) {
            ldsm4(BH[j], st + TILE_BH + sw16(warp_n + j * 16 + brow, bcx));
            ldsm4(BL[j], st + TILE_BL + sw16(warp_n + j * 16 + brow, bcx));
        }
#pragma unroll
        for (int i = 0; i < 4; i++) {
            uint32_t AHr[4], ALr[4];
            ldsm4(AHr, st + TILE_AH + sw16(warp_m + i * 16 + arow, acx));
            ldsm4(ALr, st + TILE_AL + sw16(warp_m + i * 16 + arow, acx));
#pragma unroll
            for (int j = 0; j < 4; j++) {
                const uint32_t bh0 = BH[j >> 1][(j & 1) * 2];
                const uint32_t bh1 = BH[j >> 1][(j & 1) * 2 + 1];
                const uint32_t bl0 = BL[j >> 1][(j & 1) * 2];
                const uint32_t bl1 = BL[j >> 1][(j & 1) * 2 + 1];
                mma16816(acc[i][j], AHr, bh0, bh1);   // hi*hi
                mma16816(acc[i][j], AHr, bl0, bl1);   // hi*lo
                mma16816(acc[i][j], ALr, bh0, bh1);   // lo*hi
            }
        }

        if (pf) {
            char* dst = smem + ((t + 1) & 1) * STAGE_SZ;
            uint4 hi, lo;
            cvt8(a0, a1, hi, lo);
            *reinterpret_cast<uint4*>(dst + TILE_AH + swoff) = hi;
            *reinterpret_cast<uint4*>(dst + TILE_AL + swoff) = lo;
            cvt8(b0, b1, hi, lo);
            *reinterpret_cast<uint4*>(dst + TILE_BH + swoff) = hi;
            *reinterpret_cast<uint4*>(dst + TILE_BL + swoff) = lo;
        }
    }

    float* Sb = S + (size_t)b * N_ * M_;
    const int tr = lane >> 2;
    const int tc = (lane & 3) * 2;
#pragma unroll
    for (int i = 0; i < 4; i++) {
#pragma unroll
        for (int j = 0; j < 4; j++) {
            const int r = warp_m + i * 16 + tr;
            const int c = warp_n + j * 8 + tc;
            *reinterpret_cast<float2*>(Sb + (size_t)(rA0 + r) * M_ + rB0 + c) =
                make_float2(acc[i][j][0], acc[i][j][1]);
            *reinterpret_cast<float2*>(Sb + (size_t)(rA0 + r + 8) * M_ + rB0 + c) =
                make_float2(acc[i][j][2], acc[i][j][3]);
        }
    }

    float* epi = reinterpret_cast<float*>(smem);   // [64][129]
    float* Stb = St + (size_t)b * N_ * M_;
    const int mc = tid & 127;
    const int q  = tid >> 7;
#pragma unroll
    for (int p = 0; p < 2; p++) {
        __syncthreads();   // p=0: last-stage ldsm done; p=1: prior pass reads done
        if ((warp >> 2) == p) {
#pragma unroll
            for (int i = 0; i < 4; i++)
#pragma unroll
                for (int j = 0; j < 4; j++) {
                    const int r = i * 16 + tr;
                    const int c = warp_n + j * 8 + tc;
                    epi[r * 129 + c]           = acc[i][j][0];
                    epi[r * 129 + c + 1]       = acc[i][j][1];
                    epi[(r + 8) * 129 + c]     = acc[i][j][2];
                    epi[(r + 8) * 129 + c + 1] = acc[i][j][3];
                }
        }
        __syncthreads();
#pragma unroll
        for (int i = 0; i < 8; i++) {
            const int n0 = q * 32 + i * 4;
            float4 v;
            v.x = epi[(n0 + 0) * 129 + mc];
            v.y = epi[(n0 + 1) * 129 + mc];
            v.z = epi[(n0 + 2) * 129 + mc];
            v.w = epi[(n0 + 3) * 129 + mc];
            *reinterpret_cast<float4*>(Stb + (size_t)(rB0 + mc) * N_ + rA0 + p * 64 + n0) = v;
        }
    }
}

// ---------------------------------------------------------------------------
// Warp-per-row fused masked softmax + near-one-hot sparse apply
// (R8 version verbatim — measured 59.5us). Both directions in one launch.
// ---------------------------------------------------------------------------
#define TAU 1e-7f
#define LCAP 512     // worst-case significant entries per row (correctness bound)

__global__ __launch_bounds__(256)
void softmax_apply3(const float* __restrict__ S, const float* __restrict__ St,
                    const int* __restrict__ mask1, const int* __restrict__ mask2,
                    const float* __restrict__ x1, const float* __restrict__ x2,
                    float* __restrict__ out)
{
    __shared__ float sp  [8][LCAP];
    __shared__ int   sidx[8][LCAP];

    const int dir  = blockIdx.y;
    const int warp = threadIdx.x >> 5;
    const int lane = threadIdx.x & 31;
    const int row  = blockIdx.x * 8 + warp;      // 0 .. B*512-1
    const int b    = row >> 9;

    const float* Sr = (dir ? St : S) + (size_t)row * 512;
    const int*   mk = (dir ? mask1 : mask2) + (size_t)b * 512;
    const float* Xb = (dir ? x1 : x2) + (size_t)b * 512 * D_;
    float*       op = out + (size_t)dir * B_ * N_ * D_ + (size_t)row * D_;

    // ---- load 16 logits/lane + mask, fold mask, find max ----
    const float4* Sr4 = reinterpret_cast<const float4*>(Sr);
    const int4*   mk4 = reinterpret_cast<const int4*>(mk);
    float v[16];
    float mx = -INFINITY;
#pragma unroll
    for (int i = 0; i < 4; i++) {
        const float4 f = Sr4[i * 32 + lane];
        const int4   m = mk4[i * 32 + lane];
        v[i * 4 + 0] = m.x ? f.x : -INFINITY;
        v[i * 4 + 1] = m.y ? f.y : -INFINITY;
        v[i * 4 + 2] = m.z ? f.z : -INFINITY;
        v[i * 4 + 3] = m.w ? f.w : -INFINITY;
        mx = fmaxf(mx, fmaxf(fmaxf(v[i*4], v[i*4+1]), fmaxf(v[i*4+2], v[i*4+3])));
    }
#pragma unroll
    for (int s = 16; s > 0; s >>= 1) mx = fmaxf(mx, __shfl_xor_sync(0xffffffffu, mx, s));

    // ---- exp + sum ----
    float sum = 0.f;
#pragma unroll
    for (int i = 0; i < 16; i++) {
        const float e = (v[i] == -INFINITY) ? 0.f : __expf(v[i] - mx);
        v[i] = e;
        sum += e;
    }
#pragma unroll
    for (int s = 16; s > 0; s >>= 1) sum += __shfl_xor_sync(0xffffffffu, sum, s);
    const float inv = 1.f / sum;

    // ---- per-warp deterministic significant list (ballot prefix) ----
    int cnt = 0;
#pragma unroll
    for (int j = 0; j < 16; j++) {
        const int i = j >> 2, c = j & 3;               // element idx = i*128 + lane*4 + c
        const float p = v[i * 4 + c] * inv;
        const bool sig = p > TAU;
        const unsigned bm = __ballot_sync(0xffffffffu, sig);
        if (sig) {
            const int pos = cnt + __popc(bm & ((1u << lane) - 1u));
            sidx[warp][pos] = i * 128 + lane * 4 + c;
            sp[warp][pos]   = p;
        }
        cnt += __popc(bm);
    }
    __syncwarp();

    // ---- gather-accumulate: out[row,:] = sum_i p_i * X[k_i,:] ----
    float4 A[8];
#pragma unroll
    for (int u = 0; u < 8; u++) A[u] = make_float4(0.f, 0.f, 0.f, 0.f);

    const float4* Xb4 = reinterpret_cast<const float4*>(Xb);
    for (int i = 0; i < cnt; i++) {
        const float p = sp[warp][i];
        const int   k = sidx[warp][i];
        const float4* xr = Xb4 + (size_t)k * (D_ / 4);
#pragma unroll
        for (int u = 0; u < 8; u++) {
            const float4 xv = xr[u * 32 + lane];
            A[u].x += p * xv.x;  A[u].y += p * xv.y;
            A[u].z += p * xv.z;  A[u].w += p * xv.w;
        }
    }

    float4* op4 = reinterpret_cast<float4*>(op);
#pragma unroll
    for (int u = 0; u < 8; u++) op4[u * 32 + lane] = A[u];
}

// ---------------------------------------------------------------------------
extern "C" void kernel_launch(void* const* d_in, const int* in_sizes, int n_in,
                              void* d_out, int out_size)
{
    const float* x1    = (const float*)d_in[0];
    const float* x2    = (const float*)d_in[1];
    const int*   mask1 = (const int*)  d_in[2];
    const int*   mask2 = (const int*)  d_in[3];

    float* out = (float*)d_out;

    float *S, *St;
    cudaGetSymbolAddress((void**)&S,  g_S);
    cudaGetSymbolAddress((void**)&St, g_St);

    cudaFuncSetAttribute(gemm_fused, cudaFuncAttributeMaxDynamicSharedMemorySize, GEMM_SMEM);

    // 1) S = x1 @ x2^T and St = S^T (R7 gemm: in-kernel fp16 hi/lo split)
    gemm_fused<<<dim3(M_ / 128, N_ / 128, B_), 256, GEMM_SMEM>>>(x1, x2, S, St);

    // 2) warp-per-row fused masked-softmax + sparse apply (R8, both dirs)
    softmax_apply3<<<dim3(B_ * N_ / 8, 2), 256>>>(S, St, mask1, mask2, x1, x2, out);
}